// round 7
// baseline (speedup 1.0000x reference)
#include <cuda_runtime.h>
#include <math.h>
#include <stdint.h>

#define HH 128
#define WW 128
#define HW (HH*WW)
#define BATCH 2
#define CC 128

// ---------------- scratch (device globals; no allocation allowed) ----------------
__device__ float g_lf0 [BATCH*HW*CC];     // channels-last [b][y][x][c]
__device__ float g_lf1 [BATCH*HW*CC];     // channels-last
__device__ float g_tmp [2*BATCH*CC*HW];   // NCHW conv intermediate (4 batches for DUAL)
__device__ float g_feat[BATCH*HW*CC];     // channels-last (1 - normalized diff)
__device__ float g_qk  [BATCH*HW*256];    // [pixel][0:128]=q, [128:256]=k
__device__ float g_fi  [BATCH*2*HW];      // NCHW
__device__ float g_d16a[BATCH*16*HW];
__device__ float g_d16b[BATCH*16*HW];
__device__ float g_flow[BATCH*2*HW];
__device__ float g_hcat[BATCH*258*HW];    // [feat0 | warped feat1 | flow]
__device__ float g_c1  [BATCH*CC*HW];
__device__ float g_c2  [BATCH*64*HW];

__device__ __forceinline__ float gelu_f(float x) {
    return 0.5f * x * (1.f + erff(x * 0.70710678118654752f));
}

// ---------------- generic 3x3 conv, pad 1 ----------------
// Block: 256 threads, spatial tile 32(rows) x 64(cols). Each thread: 2x4 pixels, CT couts.
// Stages 2 input channels per barrier round (CIN must be even); staging addresses
// are precomputed once (loop-invariant across channel rounds).
// ACT: 0=none 1=gelu 2=sigmoid. OUT_CL: channels-last output. RESID: out = resid + conv.
// DUAL: blockIdx.z in [0,2*BATCH); z >= BATCH uses (in2, out2) with b = z - BATCH.
template<int CIN, int NCOUT, int CT, int ACT, bool OUT_CL, bool RESID, bool DUAL>
__global__ __launch_bounds__(256, 2)
void conv3x3_k(const float* __restrict__ in, const float* __restrict__ wt,
               const float* __restrict__ bias, float* __restrict__ out,
               const float* __restrict__ resid,
               const float* __restrict__ in2, float* __restrict__ out2)
{
    __shared__ float sp[2][34*66];
    __shared__ float sw[2][CT*9];
    const int tid  = threadIdx.x;
    const int tileY = blockIdx.x >> 1;      // 4 row tiles
    const int tileX = blockIdx.x & 1;       // 2 col tiles
    const int y0 = tileY * 32, x0 = tileX * 64;
    const int co0 = blockIdx.y * CT;
    const int bz  = blockIdx.z;
    int b = bz;
    const float* src = in;
    float* dst = out;
    if (DUAL && bz >= BATCH) { src = in2; dst = out2; b = bz - BATCH; }
    const int ty = tid >> 4, tx = tid & 15;
    const int oy = y0 + 2*ty, ox = x0 + 4*tx;

    // precompute staging offsets once: goff[s] = plane offset, -1 if OOB/past-end
    constexpr int NSTAGE = (34*66 + 255) / 256;   // 9
    int goff[NSTAGE];
    #pragma unroll
    for (int s = 0; s < NSTAGE; s++) {
        int idx = tid + s*256;
        int pr = idx / 66, pc = idx % 66;
        int gy = y0 + pr - 1, gx = x0 + pc - 1;
        bool ok = (idx < 34*66) && gy >= 0 && gy < HH && gx >= 0 && gx < WW;
        goff[s] = ok ? (gy*WW + gx) : -1;
    }

    float acc[CT][8];
    #pragma unroll
    for (int c = 0; c < CT; c++)
        #pragma unroll
        for (int q = 0; q < 8; q++) acc[c][q] = 0.f;

    static_assert(CIN % 2 == 0, "CIN must be even");
    static_assert(2*CT*9 <= 256, "weight staging fits one round");
    for (int ci = 0; ci < CIN; ci += 2) {
        // stage two input planes + their weights, one barrier round
        #pragma unroll
        for (int pl = 0; pl < 2; pl++) {
            const float* plane = src + (size_t)(b*CIN + ci + pl) * HW;
            #pragma unroll
            for (int s = 0; s < NSTAGE; s++) {
                int idx = tid + s*256;
                if (idx < 34*66)
                    sp[pl][idx] = (goff[s] >= 0) ? plane[goff[s]] : 0.f;
            }
        }
        if (tid < 2*CT*9) {
            int pl = tid / (CT*9), r = tid % (CT*9);
            sw[pl][r] = wt[((size_t)(co0 + r/9) * CIN + ci + pl) * 9 + r % 9];
        }
        __syncthreads();

        #pragma unroll
        for (int pl = 0; pl < 2; pl++) {
            float pv[4][6];
            #pragma unroll
            for (int i = 0; i < 4; i++)
                #pragma unroll
                for (int j = 0; j < 6; j++)
                    pv[i][j] = sp[pl][(2*ty + i)*66 + 4*tx + j];

            #pragma unroll
            for (int c = 0; c < CT; c++) {
                float w0 = sw[pl][c*9+0], w1 = sw[pl][c*9+1], w2 = sw[pl][c*9+2];
                float w3 = sw[pl][c*9+3], w4 = sw[pl][c*9+4], w5 = sw[pl][c*9+5];
                float w6 = sw[pl][c*9+6], w7 = sw[pl][c*9+7], w8 = sw[pl][c*9+8];
                #pragma unroll
                for (int dy = 0; dy < 2; dy++)
                    #pragma unroll
                    for (int dx = 0; dx < 4; dx++) {
                        float s = w0*pv[dy  ][dx] + w1*pv[dy  ][dx+1] + w2*pv[dy  ][dx+2]
                                + w3*pv[dy+1][dx] + w4*pv[dy+1][dx+1] + w5*pv[dy+1][dx+2]
                                + w6*pv[dy+2][dx] + w7*pv[dy+2][dx+1] + w8*pv[dy+2][dx+2];
                        acc[c][dy*4 + dx] += s;
                    }
            }
        }
        __syncthreads();
    }

    #pragma unroll
    for (int c = 0; c < CT; c++) {
        float bv = bias[co0 + c];
        #pragma unroll
        for (int dy = 0; dy < 2; dy++)
            #pragma unroll
            for (int dx = 0; dx < 4; dx++) {
                int gy = oy + dy, gx = ox + dx;
                float v = acc[c][dy*4 + dx] + bv;
                size_t oidx;
                if (OUT_CL) oidx = ((size_t)(b*HW) + gy*WW + gx) * NCOUT + co0 + c;
                else        oidx = ((size_t)(b*NCOUT + co0 + c)) * HW + gy*WW + gx;
                if (RESID) v += resid[oidx];
                if (ACT == 1) v = gelu_f(v);
                else if (ACT == 2) v = 1.f / (1.f + expf(-v));
                dst[oidx] = v;
            }
    }
}

// ---------------- fused warp(lf1,flow), diff, L2-normalize, 1-diff ----------------
// grid (HW/2, B), block 256: two pixels per block (128 threads each). Channels-last io.
__global__ __launch_bounds__(256)
void warp_diff_feat_k(const float* __restrict__ lf0,
                      const float* __restrict__ lf1,
                      const float* __restrict__ flow,
                      float* __restrict__ feat)
{
    const int half = threadIdx.x >> 7;            // 0 or 1: which pixel
    const int c    = threadIdx.x & 127;           // channel
    const int p    = blockIdx.x * 2 + half;
    const int b    = blockIdx.y;
    const int y = p >> 7, x = p & 127;

    float fx = flow[(b*2 + 0)*HW + p];
    float fy = flow[(b*2 + 1)*HW + p];
    float xx = fminf(fmaxf((float)x + fx, 0.f), 127.f);
    float yy = fminf(fmaxf((float)y + fy, 0.f), 127.f);
    float x0f = floorf(xx), y0f = floorf(yy);
    int x0 = (int)x0f, y0 = (int)y0f;
    int x1 = min(x0 + 1, 127), y1 = min(y0 + 1, 127);
    float wx = xx - x0f, wy = yy - y0f;

    const float* base = lf1 + (size_t)b * HW * CC;
    float v00 = base[((size_t)(y0*WW + x0))*CC + c];
    float v01 = base[((size_t)(y0*WW + x1))*CC + c];
    float v10 = base[((size_t)(y1*WW + x0))*CC + c];
    float v11 = base[((size_t)(y1*WW + x1))*CC + c];
    float wv = v00*(1.f-wx)*(1.f-wy) + v01*wx*(1.f-wy)
             + v10*(1.f-wx)*wy       + v11*wx*wy;

    float d = lf0[((size_t)(b*HW) + p)*CC + c] - wv;

    float ss = d * d;
    #pragma unroll
    for (int o = 16; o; o >>= 1) ss += __shfl_xor_sync(0xffffffffu, ss, o);
    __shared__ float wsum[2][4];
    if ((c & 31) == 0) wsum[half][c >> 5] = ss;
    __syncthreads();
    float tot = wsum[half][0] + wsum[half][1] + wsum[half][2] + wsum[half][3];
    float denom = fmaxf(sqrtf(tot), 1e-12f);

    feat[((size_t)(b*HW) + p)*CC + c] = 1.f - d / denom;
}

// ---------------- q/k 1x1 conv as GEMM: [32768 x 128] x [128 x 128]^T ----------------
// grid (M/128, 2[q|k]); block 256; 8x8 register tile.
__global__ __launch_bounds__(256)
void qk_gemm_k(const float* __restrict__ A,
               const float* __restrict__ qw, const float* __restrict__ qb,
               const float* __restrict__ kw, const float* __restrict__ kb,
               float* __restrict__ out)
{
    __shared__ float As[16][132];
    __shared__ float Bs[16][132];
    const int tid = threadIdx.x;
    const int m0  = blockIdx.x * 128;
    const float* Wm = blockIdx.y ? kw : qw;
    const float* bb = blockIdx.y ? kb : qb;
    const int off   = blockIdx.y ? 128 : 0;
    const int tm = tid >> 4, tn = tid & 15;

    float acc[8][8];
    #pragma unroll
    for (int i = 0; i < 8; i++)
        #pragma unroll
        for (int j = 0; j < 8; j++) acc[i][j] = 0.f;

    for (int k0 = 0; k0 < 128; k0 += 16) {
        for (int i = tid; i < 128*16; i += 256) {
            int m = i >> 4, kk = i & 15;
            As[kk][m] = A [(size_t)(m0 + m)*128 + k0 + kk];
            Bs[kk][m] = Wm[(size_t)m*128 + k0 + kk];
        }
        __syncthreads();
        #pragma unroll
        for (int kk = 0; kk < 16; kk++) {
            float a[8], bv[8];
            #pragma unroll
            for (int i = 0; i < 8; i++) a[i]  = As[kk][tm*8 + i];
            #pragma unroll
            for (int j = 0; j < 8; j++) bv[j] = Bs[kk][tn*8 + j];
            #pragma unroll
            for (int i = 0; i < 8; i++)
                #pragma unroll
                for (int j = 0; j < 8; j++)
                    acc[i][j] += a[i] * bv[j];
        }
        __syncthreads();
    }
    #pragma unroll
    for (int j = 0; j < 8; j++) {
        float bvv = bb[tn*8 + j];
        #pragma unroll
        for (int i = 0; i < 8; i++)
            out[(size_t)(m0 + tm*8 + i)*256 + off + tn*8 + j] = acc[i][j] + bvv;
    }
}

// ---------------- local 5x5 window attention ----------------
// 1 warp per pixel. q/k channels-last in g_qk. Zero-padded window semantics.
__global__ void attn_k(const float* __restrict__ qk,
                       const float* __restrict__ flow,
                       float* __restrict__ fi)
{
    const int warp = threadIdx.x >> 5;
    const int lane = threadIdx.x & 31;
    const int p = blockIdx.x * 8 + warp;
    const int b = blockIdx.y;
    const int y = p >> 7, x = p & 127;

    const float4* qptr = (const float4*)(qk + ((size_t)(b*HW) + p)*256);
    float4 q4 = qptr[lane];

    float sc[25];
    #pragma unroll
    for (int j = 0; j < 25; j++) {
        int dy = j/5 - 2, dx = j%5 - 2;
        int ny = y + dy, nx = x + dx;
        bool inb = (ny >= 0 && ny < HH && nx >= 0 && nx < WW);
        float s = 0.f;
        if (inb) {
            const float4* kp = (const float4*)(qk + ((size_t)(b*HW) + ny*WW + nx)*256 + 128);
            float4 k4 = kp[lane];
            s = q4.x*k4.x + q4.y*k4.y + q4.z*k4.z + q4.w*k4.w;
        }
        #pragma unroll
        for (int o = 16; o; o >>= 1) s += __shfl_xor_sync(0xffffffffu, s, o);
        sc[j] = inb ? s * 0.08838834764831845f : 0.f;   // 1/sqrt(128)
    }
    float m = sc[0];
    #pragma unroll
    for (int j = 1; j < 25; j++) m = fmaxf(m, sc[j]);
    float sum = 0.f;
    #pragma unroll
    for (int j = 0; j < 25; j++) { sc[j] = expf(sc[j] - m); sum += sc[j]; }
    float inv = 1.f / sum;

    float ox = 0.f, oyv = 0.f;
    #pragma unroll
    for (int j = 0; j < 25; j++) {
        int dy = j/5 - 2, dx = j%5 - 2;
        int ny = y + dy, nx = x + dx;
        if (ny >= 0 && ny < HH && nx >= 0 && nx < WW) {
            float pr = sc[j] * inv;
            ox  += pr * flow[(b*2 + 0)*HW + ny*WW + nx];
            oyv += pr * flow[(b*2 + 1)*HW + ny*WW + nx];
        }
    }
    if (lane == 0) {
        fi[(b*2 + 0)*HW + p] = ox;
        fi[(b*2 + 1)*HW + p] = oyv;
    }
}

// ---------------- build hcat = [feat0 | warp(feat1, flow) | flow] in one pass ----------------
// grid (HW/256, 258, B). c<128: copy feat0; 128<=c<256: bilinear warp feat1; c>=256: copy flow.
__global__ void build_hcat_k(const float* __restrict__ feat0,
                             const float* __restrict__ feat1,
                             const float* __restrict__ flow,
                             float* __restrict__ hcat)
{
    const int p = blockIdx.x * 256 + threadIdx.x;
    const int c = blockIdx.y, b = blockIdx.z;
    float* dstp = hcat + ((size_t)(b*258 + c))*HW + p;

    if (c < 128) {
        *dstp = feat0[((size_t)(b*CC + c))*HW + p];
        return;
    }
    if (c >= 256) {
        *dstp = flow[((size_t)(b*2 + (c - 256)))*HW + p];
        return;
    }
    const int cc = c - 128;
    const int y = p >> 7, x = p & 127;
    float fx = flow[(b*2 + 0)*HW + p];
    float fy = flow[(b*2 + 1)*HW + p];
    float xx = fminf(fmaxf((float)x + fx, 0.f), 127.f);
    float yy = fminf(fmaxf((float)y + fy, 0.f), 127.f);
    float x0f = floorf(xx), y0f = floorf(yy);
    int x0 = (int)x0f, y0 = (int)y0f;
    int x1 = min(x0 + 1, 127), y1 = min(y0 + 1, 127);
    float wx = xx - x0f, wy = yy - y0f;

    const float* plane = feat1 + (size_t)(b*CC + cc) * HW;
    float v00 = plane[y0*WW + x0];
    float v01 = plane[y0*WW + x1];
    float v10 = plane[y1*WW + x0];
    float v11 = plane[y1*WW + x1];
    *dstp = v00*(1.f-wx)*(1.f-wy) + v01*wx*(1.f-wy)
          + v10*(1.f-wx)*wy       + v11*wx*wy;
}

// ---------------- launch ----------------
extern "C" void kernel_launch(void* const* d_in, const int* in_sizes, int n_in,
                              void* d_out, int out_size)
{
    const float* feat0     = (const float*)d_in[0];
    const float* feat1     = (const float*)d_in[1];
    const float* flow_init = (const float*)d_in[2];
    const float* lc_w1 = (const float*)d_in[3];
    const float* lc_b1 = (const float*)d_in[4];
    const float* lc_w2 = (const float*)d_in[5];
    const float* lc_b2 = (const float*)d_in[6];
    const float* qw    = (const float*)d_in[7];
    const float* qb    = (const float*)d_in[8];
    const float* kw    = (const float*)d_in[9];
    const float* kb    = (const float*)d_in[10];
    const float* fr_w1 = (const float*)d_in[11];
    const float* fr_b1 = (const float*)d_in[12];
    const float* fr_w2 = (const float*)d_in[13];
    const float* fr_b2 = (const float*)d_in[14];
    const float* fr_w3 = (const float*)d_in[15];
    const float* fr_b3 = (const float*)d_in[16];
    const float* cf_w1 = (const float*)d_in[17];
    const float* cf_b1 = (const float*)d_in[18];
    const float* cf_w2 = (const float*)d_in[19];
    const float* cf_b2 = (const float*)d_in[20];
    const float* cf_w3 = (const float*)d_in[21];
    const float* cf_b3 = (const float*)d_in[22];

    float *lf0, *lf1, *tmp, *feat, *qkb, *fi, *d16a, *d16b, *flow, *hcat, *c1, *c2;
    cudaGetSymbolAddress((void**)&lf0,  g_lf0);
    cudaGetSymbolAddress((void**)&lf1,  g_lf1);
    cudaGetSymbolAddress((void**)&tmp,  g_tmp);
    cudaGetSymbolAddress((void**)&feat, g_feat);
    cudaGetSymbolAddress((void**)&qkb,  g_qk);
    cudaGetSymbolAddress((void**)&fi,   g_fi);
    cudaGetSymbolAddress((void**)&d16a, g_d16a);
    cudaGetSymbolAddress((void**)&d16b, g_d16b);
    cudaGetSymbolAddress((void**)&flow, g_flow);
    cudaGetSymbolAddress((void**)&hcat, g_hcat);
    cudaGetSymbolAddress((void**)&c1,   g_c1);
    cudaGetSymbolAddress((void**)&c2,   g_c2);

    float* tmpB = tmp + (size_t)BATCH*CC*HW;   // second feature's intermediate

    cudaMemcpyAsync(flow, flow_init, (size_t)BATCH*2*HW*sizeof(float),
                    cudaMemcpyDeviceToDevice, 0);

    const dim3 blk(256);

    // local_conv on both features, batch-merged (DUAL): z in [0,4)
    conv3x3_k<128,128,8,1,false,false,true><<<dim3(8,16,4), blk>>>(
        feat0, lc_w1, lc_b1, tmp, nullptr, feat1, tmpB);
    conv3x3_k<128,128,8,0,true ,false,true><<<dim3(8,16,4), blk>>>(
        tmp,   lc_w2, lc_b2, lf0, nullptr, tmpB, lf1);

    for (int it = 0; it < 10; ++it) {
        warp_diff_feat_k<<<dim3(HW/2, 2), 256>>>(lf0, lf1, flow, feat);
        qk_gemm_k<<<dim3(BATCH*HW/128, 2), 256>>>(feat, qw, qb, kw, kb, qkb);
        attn_k<<<dim3(HW/8, 2), 256>>>(qkb, flow, fi);
        // latency-bound small convs: small CT => more blocks in flight
        conv3x3_k<2 ,16,4,1,false,false,false><<<dim3(8,4,2), blk>>>(
            fi,   fr_w1, fr_b1, d16a, nullptr, nullptr, nullptr);
        conv3x3_k<16,16,4,1,false,false,false><<<dim3(8,4,2), blk>>>(
            d16a, fr_w2, fr_b2, d16b, nullptr, nullptr, nullptr);
        conv3x3_k<16,2 ,1,0,false,true ,false><<<dim3(8,2,2), blk>>>(
            d16b, fr_w3, fr_b3, flow, flow, nullptr, nullptr);
    }

    // confidence head: hcat built in a single kernel (no memcpy nodes)
    build_hcat_k<<<dim3(HW/256, 258, 2), 256>>>(feat0, feat1, flow, hcat);

    float* conf_out = (float*)d_out + (size_t)BATCH*2*HW;
    conv3x3_k<258,128,8,1,false,false,false><<<dim3(8,16,2), blk>>>(
        hcat, cf_w1, cf_b1, c1, nullptr, nullptr, nullptr);
    conv3x3_k<128,64 ,8,1,false,false,false><<<dim3(8,8 ,2), blk>>>(
        c1,   cf_w2, cf_b2, c2, nullptr, nullptr, nullptr);
    conv3x3_k<64 ,1  ,1,2,false,false,false><<<dim3(8,1 ,2), blk>>>(
        c2,   cf_w3, cf_b3, conf_out, nullptr, nullptr, nullptr);

    // output: flow first, conf second
    cudaMemcpyAsync(d_out, flow, (size_t)BATCH*2*HW*sizeof(float),
                    cudaMemcpyDeviceToDevice, 0);
}